// round 1
// baseline (speedup 1.0000x reference)
#include <cuda_runtime.h>

// Problem constants
#define NB   32
#define C    4096
#define HW   784        // 28*28
#define HW4  196        // HW / 4 (float4 granularity)
#define NO   4          // output channels
#define CHUNKS 16
#define CC   (C / CHUNKS)   // 256 channels per chunk

// Scratch (no allocation allowed): pre-relu cam accumulators + mean map
__device__ float g_cams[NB * NO * HW];   // 401,408 B
__device__ float g_mean[NB * HW];        // 100,352 B

// ---------------------------------------------------------------------------
// Kernel 0: zero the cam accumulators (d_out is poisoned; scratch too)
// ---------------------------------------------------------------------------
__global__ void k0_zero() {
    int i = blockIdx.x * blockDim.x + threadIdx.x;
    if (i < NB * NO * HW) g_cams[i] = 0.0f;
}

// ---------------------------------------------------------------------------
// Kernel 1: partial dot products. block = (c_chunk, n). 256 threads.
// Threads 0..195 each own one float4 (4 hw positions); loop 256 channels,
// accumulate 4 outputs x 4 positions, atomicAdd into g_cams.
// ---------------------------------------------------------------------------
__global__ __launch_bounds__(256) void k1_dot(const float* __restrict__ x,
                                              const float* __restrict__ w) {
    const int cchunk = blockIdx.x;
    const int n      = blockIdx.y;
    const int tid    = threadIdx.x;

    __shared__ float sw[NO][CC];
    for (int i = tid; i < NO * CC; i += 256) {
        int o = i / CC, c = i % CC;
        sw[o][c] = w[o * C + cchunk * CC + c];
    }
    __syncthreads();

    if (tid >= HW4) return;

    float a00 = 0.f, a01 = 0.f, a02 = 0.f, a03 = 0.f;
    float a10 = 0.f, a11 = 0.f, a12 = 0.f, a13 = 0.f;
    float a20 = 0.f, a21 = 0.f, a22 = 0.f, a23 = 0.f;
    float a30 = 0.f, a31 = 0.f, a32 = 0.f, a33 = 0.f;

    const float* xb = x + ((size_t)n * C + (size_t)cchunk * CC) * HW + tid * 4;

#pragma unroll 4
    for (int c = 0; c < CC; c++) {
        float4 xv = *(const float4*)(xb + (size_t)c * HW);
        float w0 = sw[0][c], w1 = sw[1][c], w2 = sw[2][c], w3 = sw[3][c];
        a00 += w0 * xv.x; a01 += w0 * xv.y; a02 += w0 * xv.z; a03 += w0 * xv.w;
        a10 += w1 * xv.x; a11 += w1 * xv.y; a12 += w1 * xv.z; a13 += w1 * xv.w;
        a20 += w2 * xv.x; a21 += w2 * xv.y; a22 += w2 * xv.z; a23 += w2 * xv.w;
        a30 += w3 * xv.x; a31 += w3 * xv.y; a32 += w3 * xv.z; a33 += w3 * xv.w;
    }

    const int hw = tid * 4;
    float* c0 = &g_cams[((size_t)n * NO + 0) * HW + hw];
    float* c1 = &g_cams[((size_t)n * NO + 1) * HW + hw];
    float* c2 = &g_cams[((size_t)n * NO + 2) * HW + hw];
    float* c3 = &g_cams[((size_t)n * NO + 3) * HW + hw];
    atomicAdd(c0 + 0, a00); atomicAdd(c0 + 1, a01); atomicAdd(c0 + 2, a02); atomicAdd(c0 + 3, a03);
    atomicAdd(c1 + 0, a10); atomicAdd(c1 + 1, a11); atomicAdd(c1 + 2, a12); atomicAdd(c1 + 3, a13);
    atomicAdd(c2 + 0, a20); atomicAdd(c2 + 1, a21); atomicAdd(c2 + 2, a22); atomicAdd(c2 + 3, a23);
    atomicAdd(c3 + 0, a30); atomicAdd(c3 + 1, a31); atomicAdd(c3 + 2, a32); atomicAdd(c3 + 3, a33);
}

// ---------------------------------------------------------------------------
// Kernel 2: relu -> per-(n,o) max -> threshold -> mean-drop map. 32 blocks.
// ---------------------------------------------------------------------------
__global__ __launch_bounds__(256) void k2_thresh(const float* __restrict__ gama_p) {
    const int n   = blockIdx.x;
    const int tid = threadIdx.x;
    const float gama = *gama_p;

    float v[NO][4];
    float lmax[NO] = {0.f, 0.f, 0.f, 0.f};   // relu outputs are >= 0

    const bool active = tid < HW4;
    if (active) {
        const int hw = tid * 4;
#pragma unroll
        for (int o = 0; o < NO; o++) {
            const float* p = &g_cams[((size_t)n * NO + o) * HW + hw];
            float4 cv = *(const float4*)p;
            v[o][0] = fmaxf(cv.x, 0.f);
            v[o][1] = fmaxf(cv.y, 0.f);
            v[o][2] = fmaxf(cv.z, 0.f);
            v[o][3] = fmaxf(cv.w, 0.f);
            lmax[o] = fmaxf(fmaxf(v[o][0], v[o][1]), fmaxf(v[o][2], v[o][3]));
        }
    }

    __shared__ float smax[NO][256];
#pragma unroll
    for (int o = 0; o < NO; o++) smax[o][tid] = lmax[o];
    __syncthreads();
    for (int s = 128; s > 0; s >>= 1) {
        if (tid < s) {
#pragma unroll
            for (int o = 0; o < NO; o++)
                smax[o][tid] = fmaxf(smax[o][tid], smax[o][tid + s]);
        }
        __syncthreads();
    }

    if (active) {
        float thr0 = smax[0][0] * gama;
        float thr1 = smax[1][0] * gama;
        float thr2 = smax[2][0] * gama;
        float thr3 = smax[3][0] * gama;
        float4 m;
        // dropped = (cam > thr) ? 0 : cam ; mean over 4 outputs
        m.x = ((v[0][0] > thr0 ? 0.f : v[0][0]) + (v[1][0] > thr1 ? 0.f : v[1][0]) +
               (v[2][0] > thr2 ? 0.f : v[2][0]) + (v[3][0] > thr3 ? 0.f : v[3][0])) * 0.25f;
        m.y = ((v[0][1] > thr0 ? 0.f : v[0][1]) + (v[1][1] > thr1 ? 0.f : v[1][1]) +
               (v[2][1] > thr2 ? 0.f : v[2][1]) + (v[3][1] > thr3 ? 0.f : v[3][1])) * 0.25f;
        m.z = ((v[0][2] > thr0 ? 0.f : v[0][2]) + (v[1][2] > thr1 ? 0.f : v[1][2]) +
               (v[2][2] > thr2 ? 0.f : v[2][2]) + (v[3][2] > thr3 ? 0.f : v[3][2])) * 0.25f;
        m.w = ((v[0][3] > thr0 ? 0.f : v[0][3]) + (v[1][3] > thr1 ? 0.f : v[1][3]) +
               (v[2][3] > thr2 ? 0.f : v[2][3]) + (v[3][3] > thr3 ? 0.f : v[3][3])) * 0.25f;
        *(float4*)&g_mean[(size_t)n * HW + tid * 4] = m;
    }
}

// ---------------------------------------------------------------------------
// Kernel 3: out = x * mean[n, hw], float4 elementwise (822 MB HBM traffic)
// ---------------------------------------------------------------------------
__global__ __launch_bounds__(256) void k3_mul(const float* __restrict__ x,
                                              float* __restrict__ out) {
    unsigned int i4 = blockIdx.x * blockDim.x + threadIdx.x;
    const unsigned int total4 = (unsigned int)NB * C * HW4;  // 25,690,112
    if (i4 >= total4) return;

    unsigned int hw4 = i4 % HW4;
    unsigned int nc  = i4 / HW4;
    unsigned int n   = nc / C;

    float4 xv = ((const float4*)x)[i4];
    float4 m  = *(const float4*)&g_mean[(size_t)n * HW + hw4 * 4];
    float4 r;
    r.x = xv.x * m.x;
    r.y = xv.y * m.y;
    r.z = xv.z * m.z;
    r.w = xv.w * m.w;
    ((float4*)out)[i4] = r;
}

// ---------------------------------------------------------------------------
extern "C" void kernel_launch(void* const* d_in, const int* in_sizes, int n_in,
                              void* d_out, int out_size) {
    const float* x    = (const float*)d_in[0];
    const float* w    = (const float*)d_in[1];
    const float* gama = (const float*)d_in[2];
    float* out        = (float*)d_out;

    // zero accumulators
    {
        int n = NB * NO * HW;
        k0_zero<<<(n + 255) / 256, 256>>>();
    }
    // partial dot products
    {
        dim3 grid(CHUNKS, NB);
        k1_dot<<<grid, 256>>>(x, w);
    }
    // threshold + mean map
    k2_thresh<<<NB, 256>>>(gama);
    // final elementwise multiply
    {
        unsigned int total4 = (unsigned int)NB * C * HW4;
        k3_mul<<<(total4 + 255) / 256, 256>>>(x, out);
    }
}